// round 9
// baseline (speedup 1.0000x reference)
#include <cuda_runtime.h>

// B=4, H=8, S=2048, D=3 (fixed by reference)
typedef unsigned long long u64;

#define S_LEN    2048
#define N_CTA    1332          // 148 SMs x 9 CTAs: exact single wave
#define THREADS  128
#define UNITS    4096          // 32 bh x 128 chunks of 16 queries
#define QPU      16            // queries per unit
#define OUT_HALF (32 * S_LEN * 3)

// tile: 1024 records x 24B = 24576 B. red aliases last 1024 B (records 981..1023).
#define SMEM_BYTES 24576
#define RED_BYTE   23552                  // byte offset of red region
#define TAIL_KEY   1962                   // first key clobbered by red
#define TAIL_N     86                     // keys 1962..2047

__device__ __forceinline__ u64 fma2(u64 a, u64 b, u64 c) {
    u64 d; asm("fma.rn.f32x2 %0, %1, %2, %3;" : "=l"(d) : "l"(a), "l"(b), "l"(c));
    return d;
}
__device__ __forceinline__ u64 mul2(u64 a, u64 b) {
    u64 d; asm("mul.rn.f32x2 %0, %1, %2;" : "=l"(d) : "l"(a), "l"(b));
    return d;
}
__device__ __forceinline__ u64 add2(u64 a, u64 b) {
    u64 d; asm("add.rn.f32x2 %0, %1, %2;" : "=l"(d) : "l"(a), "l"(b));
    return d;
}
__device__ __forceinline__ u64 ex2_2(u64 x) {
    u64 r;
    asm("{\n\t"
        ".reg .f32 lo, hi;\n\t"
        "mov.b64 {lo, hi}, %1;\n\t"
        "ex2.approx.f32 lo, lo;\n\t"
        "ex2.approx.f32 hi, hi;\n\t"
        "mov.b64 %0, {lo, hi};\n\t"
        "}" : "=l"(r) : "l"(x));
    return r;
}
__device__ __forceinline__ u64 pack2(float lo, float hi) {
    u64 r; asm("mov.b64 %0, {%1, %2};" : "=l"(r) : "f"(lo), "f"(hi));
    return r;
}
__device__ __forceinline__ void unpack2(u64 v, float& lo, float& hi) {
    asm("mov.b64 {%0, %1}, %2;" : "=f"(lo), "=f"(hi) : "l"(v));
}
__device__ __forceinline__ float rcpa(float x) {
    float r; asm("rcp.approx.f32 %0, %1;" : "=f"(r) : "f"(x));
    return r;
}
__device__ __forceinline__ u64 lds64(unsigned addr) {
    u64 v; asm("ld.shared.b64 %0, [%1];" : "=l"(v) : "r"(addr));
    return v;
}
__device__ __forceinline__ void store_rec(float* sm, int k, float x0, float x1, float x2) {
    const int j = k >> 1, c = k & 1;
    sm[j * 6 + 0 + c] = x0;
    sm[j * 6 + 2 + c] = x1;
    sm[j * 6 + 4 + c] = x2;
}

__global__ __launch_bounds__(THREADS, 9)
void attn3d_kernel(const float* __restrict__ x,
                   const float* __restrict__ Wq,
                   const float* __restrict__ Wk,
                   const float* __restrict__ Wv,
                   float* __restrict__ out)
{
    extern __shared__ float sm[];
    float4* red4 = reinterpret_cast<float4*>(reinterpret_cast<char*>(sm) + RED_BYTE);

    const int tid  = threadIdx.x;
    const int cta  = blockIdx.x;
    const int w    = tid >> 5;        // warp 0..3: keys [w*512, (w+1)*512)
    const int lane = tid & 31;
    const int q    = lane & 15;       // query slot within unit
    const int sub  = lane >> 4;       // half-split of the warp's keys

    unsigned sbase;
    asm("{ .reg .u64 t; cvta.to.shared.u64 t, %1; cvt.u32.u64 %0, t; }"
        : "=r"(sbase) : "l"(sm));
    // this lane's 128 records (256 keys)
    const unsigned pstart = sbase + (unsigned)(w * 256 + sub * 128) * 24u;

    const int u0 = (int)(((long long)cta * UNITS) / N_CTA);
    const int u1 = (int)(((long long)(cta + 1) * UNITS) / N_CTA);

    const float RS = 0.57735026918962576f * 1.4426950408889634f;
    int cur_bh = -1;

    for (int u = u0; u < u1; ++u) {
        const int bh    = u >> 7;
        const int chunk = u & 127;
        const int b     = bh >> 3;
        const int h     = bh & 7;
        const float* xb = x + (size_t)b * S_LEN * 3;

        __syncthreads();              // prior unit fully consumed tile + red
        if (bh != cur_bh) {
            // full tile load
            #pragma unroll
            for (int i = 0; i < S_LEN / THREADS; ++i) {
                const int k = tid + i * THREADS;
                store_rec(sm, k, xb[k * 3 + 0], xb[k * 3 + 1], xb[k * 3 + 2]);
            }
            cur_bh = bh;
        } else if (tid < TAIL_N) {
            // restore the red-clobbered tail records
            const int k = TAIL_KEY + tid;
            store_rec(sm, k, xb[k * 3 + 0], xb[k * 3 + 1], xb[k * 3 + 2]);
        }

        // per-lane query constants (fold Wq*Wk*scale; no shift — range-safe)
        const float* wq = Wq + h * 9;
        const float* wk = Wk + h * 9;
        const int sq = chunk * QPU + q;
        const float xq0 = xb[sq * 3 + 0];
        const float xq1 = xb[sq * 3 + 1];
        const float xq2 = xb[sq * 3 + 2];
        const float q0 = xq0 * wq[0] + xq1 * wq[3] + xq2 * wq[6];
        const float q1 = xq0 * wq[1] + xq1 * wq[4] + xq2 * wq[7];
        const float q2 = xq0 * wq[2] + xq1 * wq[5] + xq2 * wq[8];
        const float a0 = RS * (q0 * wk[0] + q1 * wk[1] + q2 * wk[2]);
        const float a1 = RS * (q0 * wk[3] + q1 * wk[4] + q2 * wk[5]);
        const float a2 = RS * (q0 * wk[6] + q1 * wk[7] + q2 * wk[8]);
        const u64 q0p = pack2(a0, a0);
        const u64 q1p = pack2(a1, a1);
        const u64 q2p = pack2(a2, a2);

        __syncthreads();              // tile ready

        // ---- inner loop: 64 iterations x 2 independent records (4 keys) ----
        unsigned p = pstart;
        u64 lacc = 0ull, t0 = 0ull, t1 = 0ull, t2 = 0ull;
        #pragma unroll 2
        for (int r = 0; r < 64; ++r) {
            const u64 A0 = lds64(p);
            const u64 A1 = lds64(p + 8);
            const u64 A2 = lds64(p + 16);
            const u64 B0 = lds64(p + 24);
            const u64 B1 = lds64(p + 32);
            const u64 B2 = lds64(p + 40);
            p += 48;
            const u64 dA = fma2(q0p, A0, fma2(q1p, A1, mul2(q2p, A2)));
            const u64 dB = fma2(q0p, B0, fma2(q1p, B1, mul2(q2p, B2)));
            const u64 pA = ex2_2(dA);
            const u64 pB = ex2_2(dB);
            lacc = add2(lacc, add2(pA, pB));
            t0   = fma2(pA, A0, fma2(pB, B0, t0));
            t1   = fma2(pA, A1, fma2(pB, B1, t1));
            t2   = fma2(pA, A2, fma2(pB, B2, t2));
        }

        // collapse packed lanes
        float la, lb, v0a, v0b, v1a, v1b, v2a, v2b;
        unpack2(lacc, la, lb);
        unpack2(t0, v0a, v0b);
        unpack2(t1, v1a, v1b);
        unpack2(t2, v2a, v2b);
        float L  = la + lb;
        float T0 = v0a + v0b;
        float T1 = v1a + v1b;
        float T2 = v2a + v2b;

        // merge sub-halves within warp
        L  += __shfl_xor_sync(0xffffffffu, L,  16);
        T0 += __shfl_xor_sync(0xffffffffu, T0, 16);
        T1 += __shfl_xor_sync(0xffffffffu, T1, 16);
        T2 += __shfl_xor_sync(0xffffffffu, T2, 16);

        __syncthreads();              // all tile reads done; safe to clobber red
        if (sub == 0)
            red4[w * 16 + q] = make_float4(L, T0, T1, T2);
        __syncthreads();

        // final 4-warp merge + Wv projection + write both output copies
        if (tid < QPU) {
            const float4 r0v = red4[tid];
            const float4 r1v = red4[16 + tid];
            const float4 r2v = red4[32 + tid];
            const float4 r3v = red4[48 + tid];
            const float Lm  = r0v.x + r1v.x + r2v.x + r3v.x;
            const float M0  = r0v.y + r1v.y + r2v.y + r3v.y;
            const float M1  = r0v.z + r1v.z + r2v.z + r3v.z;
            const float M2  = r0v.w + r1v.w + r2v.w + r3v.w;
            const float inv = rcpa(Lm);
            const float* wv = Wv + h * 9;
            const float o0 = (M0 * wv[0] + M1 * wv[3] + M2 * wv[6]) * inv;
            const float o1 = (M0 * wv[1] + M1 * wv[4] + M2 * wv[7]) * inv;
            const float o2 = (M0 * wv[2] + M1 * wv[5] + M2 * wv[8]) * inv;
            const int base = (bh * S_LEN + chunk * QPU + tid) * 3;
            out[base + 0] = o0;
            out[base + 1] = o1;
            out[base + 2] = o2;
            out[OUT_HALF + base + 0] = o0;
            out[OUT_HALF + base + 1] = o1;
            out[OUT_HALF + base + 2] = o2;
        }
    }
}

extern "C" void kernel_launch(void* const* d_in, const int* in_sizes, int n_in,
                              void* d_out, int out_size)
{
    const float* x  = (const float*)d_in[0];
    const float* Wq = (const float*)d_in[1];
    const float* Wk = (const float*)d_in[2];
    const float* Wv = (const float*)d_in[3];
    float* out = (float*)d_out;

    cudaFuncSetAttribute(attn3d_kernel,
                         cudaFuncAttributeMaxDynamicSharedMemorySize, SMEM_BYTES);
    attn3d_kernel<<<N_CTA, THREADS, SMEM_BYTES>>>(x, Wq, Wk, Wv, out);
}

// round 10
// speedup vs baseline: 1.2185x; 1.2185x over previous
#include <cuda_runtime.h>

// B=4, H=8, S=2048, D=3 (fixed by reference)
typedef unsigned long long u64;

#define S_LEN   2048
#define QPC     64            // queries per CTA
#define THREADS 128           // 4 key-groups x 32 lanes (1 warp = 1 group); 2 queries/thread
#define N_CTA   1024          // 32 bh * 32 chunks
#define GROUPS  4
#define QPT     2
#define QUADS   128           // 4-key records per group (512 keys/group)
#define GSTRIDE 6160          // 128*48 + 16 pad (bank spread between groups)
#define OUT_HALF (32 * S_LEN * 3)
#define SMEM_BYTES (GROUPS * GSTRIDE)   // 24640 B

__device__ __forceinline__ u64 fma2(u64 a, u64 b, u64 c) {
    u64 d; asm("fma.rn.f32x2 %0, %1, %2, %3;" : "=l"(d) : "l"(a), "l"(b), "l"(c));
    return d;
}
__device__ __forceinline__ u64 mul2(u64 a, u64 b) {
    u64 d; asm("mul.rn.f32x2 %0, %1, %2;" : "=l"(d) : "l"(a), "l"(b));
    return d;
}
__device__ __forceinline__ u64 add2(u64 a, u64 b) {
    u64 d; asm("add.rn.f32x2 %0, %1, %2;" : "=l"(d) : "l"(a), "l"(b));
    return d;
}
__device__ __forceinline__ u64 ex2_2(u64 x) {
    u64 r;
    asm("{\n\t"
        ".reg .f32 lo, hi;\n\t"
        "mov.b64 {lo, hi}, %1;\n\t"
        "ex2.approx.f32 lo, lo;\n\t"
        "ex2.approx.f32 hi, hi;\n\t"
        "mov.b64 %0, {lo, hi};\n\t"
        "}" : "=l"(r) : "l"(x));
    return r;
}
__device__ __forceinline__ u64 pack2(float lo, float hi) {
    u64 r; asm("mov.b64 %0, {%1, %2};" : "=l"(r) : "f"(lo), "f"(hi));
    return r;
}
__device__ __forceinline__ void unpack2(u64 v, float& lo, float& hi) {
    asm("mov.b64 {%0, %1}, %2;" : "=f"(lo), "=f"(hi) : "l"(v));
}
__device__ __forceinline__ float rcpa(float x) {
    float r; asm("rcp.approx.f32 %0, %1;" : "=f"(r) : "f"(x));
    return r;
}
// LDS.128 -> two u64 halves (keys {0,1} in .x-style lo, keys {2,3} in hi)
__device__ __forceinline__ void ld2(u64& a, u64& b, unsigned addr) {
    asm("ld.shared.v2.b64 {%0, %1}, [%2];" : "=l"(a), "=l"(b) : "r"(addr));
}

__global__ __launch_bounds__(THREADS, 7)
void attn3d_kernel(const float* __restrict__ x,
                   const float* __restrict__ Wq,
                   const float* __restrict__ Wk,
                   const float* __restrict__ Wv,
                   float* __restrict__ out)
{
    extern __shared__ float sm[];
    float* red = sm;   // aliases x region after post-loop barrier (1024 floats)

    const int tid   = threadIdx.x;
    const int cta   = blockIdx.x;
    const int bh    = cta >> 5;
    const int chunk = cta & 31;
    const int b     = bh >> 3;
    const int h     = bh & 7;

    const float* xb = x + (size_t)b * S_LEN * 3;

    // ---- Fill smem: 4-key quad records [x0 x4][x1 x4][x2 x4], 48B each ----
    #pragma unroll
    for (int i = 0; i < S_LEN / THREADS; ++i) {
        const int k  = tid + i * THREADS;
        const int g  = k >> 9;             // key group (512 keys each)
        const int jc = k & 511;
        const int j  = jc >> 2;            // quad in group
        const int c  = jc & 3;             // lane in quad
        float* rec = reinterpret_cast<float*>(
            reinterpret_cast<char*>(sm) + g * GSTRIDE + j * 48);
        rec[0 + c] = xb[k * 3 + 0];
        rec[4 + c] = xb[k * 3 + 1];
        rec[8 + c] = xb[k * 3 + 2];
    }

    // ---- 2 queries per thread; fold Wq*Wk*scale; no shift (range-safe, validated) ----
    const int g  = tid >> 5;          // key group == warp id
    const int ql = tid & 31;          // query slot; handles ql and ql+32
    const float* wq = Wq + h * 9;
    const float* wk = Wk + h * 9;
    const float RS = 0.57735026918962576f * 1.4426950408889634f;

    u64 q0p[QPT], q1p[QPT], q2p[QPT];
    #pragma unroll
    for (int qq = 0; qq < QPT; ++qq) {
        const int sq = chunk * QPC + ql + qq * 32;
        const float xq0 = xb[sq * 3 + 0];
        const float xq1 = xb[sq * 3 + 1];
        const float xq2 = xb[sq * 3 + 2];
        const float q0 = xq0 * wq[0] + xq1 * wq[3] + xq2 * wq[6];
        const float q1 = xq0 * wq[1] + xq1 * wq[4] + xq2 * wq[7];
        const float q2 = xq0 * wq[2] + xq1 * wq[5] + xq2 * wq[8];
        const float a0 = RS * (q0 * wk[0] + q1 * wk[1] + q2 * wk[2]);
        const float a1 = RS * (q0 * wk[3] + q1 * wk[4] + q2 * wk[5]);
        const float a2 = RS * (q0 * wk[6] + q1 * wk[7] + q2 * wk[8]);
        q0p[qq] = pack2(a0, a0);
        q1p[qq] = pack2(a1, a1);
        q2p[qq] = pack2(a2, a2);
    }

    __syncthreads();

    unsigned sbase;
    asm("{ .reg .u64 t; cvta.to.shared.u64 t, %1; cvt.u32.u64 %0, t; }"
        : "=r"(sbase) : "l"(sm));
    unsigned p = sbase + g * GSTRIDE;

    u64 lacc[QPT] = {0ull, 0ull};
    u64 t0[QPT]   = {0ull, 0ull};
    u64 t1[QPT]   = {0ull, 0ull};
    u64 t2[QPT]   = {0ull, 0ull};

    // ---- Inner loop: one 4-key quad per body (3x LDS.128), unroll 4 ----
    #pragma unroll 4
    for (int r = 0; r < QUADS; ++r) {
        u64 X0a, X0b, X1a, X1b, X2a, X2b;
        ld2(X0a, X0b, p);
        ld2(X1a, X1b, p + 16);
        ld2(X2a, X2b, p + 32);
        p += 48;
        #pragma unroll
        for (int qq = 0; qq < QPT; ++qq) {
            const u64 dA = fma2(q0p[qq], X0a, fma2(q1p[qq], X1a, mul2(q2p[qq], X2a)));
            const u64 dB = fma2(q0p[qq], X0b, fma2(q1p[qq], X1b, mul2(q2p[qq], X2b)));
            const u64 pA = ex2_2(dA);
            const u64 pB = ex2_2(dB);
            lacc[qq] = add2(lacc[qq], add2(pA, pB));
            t0[qq]   = fma2(pA, X0a, fma2(pB, X0b, t0[qq]));
            t1[qq]   = fma2(pA, X1a, fma2(pB, X1b, t1[qq]));
            t2[qq]   = fma2(pA, X2a, fma2(pB, X2b, t2[qq]));
        }
    }

    // ---- All reads done; alias smem for reduction ----
    __syncthreads();
    #pragma unroll
    for (int qq = 0; qq < QPT; ++qq) {
        const int q = ql + qq * 32;
        float a, c;
        unpack2(lacc[qq], a, c); red[0 * 256 + g * 64 + q] = a + c;
        unpack2(t0[qq],   a, c); red[1 * 256 + g * 64 + q] = a + c;
        unpack2(t1[qq],   a, c); red[2 * 256 + g * 64 + q] = a + c;
        unpack2(t2[qq],   a, c); red[3 * 256 + g * 64 + q] = a + c;
    }
    __syncthreads();

    // ---- 4-way group merge + Wv projection + write both output copies ----
    if (tid < QPC) {
        const float L  = red[0 * 256 + tid] + red[0 * 256 + 64 + tid]
                       + red[0 * 256 + 128 + tid] + red[0 * 256 + 192 + tid];
        const float T0 = red[1 * 256 + tid] + red[1 * 256 + 64 + tid]
                       + red[1 * 256 + 128 + tid] + red[1 * 256 + 192 + tid];
        const float T1 = red[2 * 256 + tid] + red[2 * 256 + 64 + tid]
                       + red[2 * 256 + 128 + tid] + red[2 * 256 + 192 + tid];
        const float T2 = red[3 * 256 + tid] + red[3 * 256 + 64 + tid]
                       + red[3 * 256 + 128 + tid] + red[3 * 256 + 192 + tid];
        const float inv = rcpa(L);
        const float* wv = Wv + h * 9;
        const float r0 = (T0 * wv[0] + T1 * wv[3] + T2 * wv[6]) * inv;
        const float r1 = (T0 * wv[1] + T1 * wv[4] + T2 * wv[7]) * inv;
        const float r2 = (T0 * wv[2] + T1 * wv[5] + T2 * wv[8]) * inv;
        const int base = (bh * S_LEN + chunk * QPC + tid) * 3;
        out[base + 0] = r0;
        out[base + 1] = r1;
        out[base + 2] = r2;
        out[OUT_HALF + base + 0] = r0;
        out[OUT_HALF + base + 1] = r1;
        out[OUT_HALF + base + 2] = r2;
    }
}

extern "C" void kernel_launch(void* const* d_in, const int* in_sizes, int n_in,
                              void* d_out, int out_size)
{
    const float* x  = (const float*)d_in[0];
    const float* Wq = (const float*)d_in[1];
    const float* Wk = (const float*)d_in[2];
    const float* Wv = (const float*)d_in[3];
    float* out = (float*)d_out;

    cudaFuncSetAttribute(attn3d_kernel,
                         cudaFuncAttributeMaxDynamicSharedMemorySize, SMEM_BYTES);
    attn3d_kernel<<<N_CTA, THREADS, SMEM_BYTES>>>(x, Wq, Wk, Wv, out);
}